// round 10
// baseline (speedup 1.0000x reference)
#include <cuda_runtime.h>
#include <cuda_fp16.h>
#include <cstdint>

// Conv2DUF via legacy mma.sync FP16 implicit GEMM (compute_103-safe).
//   x: [32,128,56,56] f32   weight: [1152,256] f32   bias: [256]   out: [32,256,56,56]
// GEMM: M=100352 (pixels), N=256 (cout), K=1152 reordered k' = (kh*3+kw)*128 + c.
// Main: CTA 128x256 (all couts), 8 warps x (64x64), BK=64, 18 stages,
//       3-stage cp.async ring (48KB/stage), 1 CTA/SM, smem-transposed epilogue.
// Warp tile 64x64 cuts ldmatrix traffic to 128B/HMMA (crossbar no longer co-binding).

namespace {
constexpr int HW = 3136;        // 56*56
constexpr int KT = 18;          // 1152/64
constexpr int STG = 49152;      // stage: A 16KB @ +0, B 32KB @ +16384
constexpr int SMEM_DYN = 3 * STG;   // 144 KB
constexpr int NXBLK = 12544;    // x-transpose blocks
constexpr int EPAD = 132;       // epilogue scratch pitch (floats)
}

__device__ __half g_xh[32 * HW * 128];   // NHWC fp16
__device__ __half g_wh[256 * 1152];      // [cout][k'] fp16

struct alignas(8) Half4 { __half2 a, b; };

__device__ __forceinline__ uint32_t s2u(const void* p) {
    uint32_t a;
    asm("{.reg .u64 t; cvta.to.shared.u64 t, %1; cvt.u32.u64 %0, t;}" : "=r"(a) : "l"(p));
    return a;
}
__device__ __forceinline__ uint32_t swz(uint32_t o) { return o ^ ((o >> 3) & 0x70); }
__device__ __forceinline__ void cp16(uint32_t dst, const void* src, int sz) {
    asm volatile("cp.async.cg.shared.global [%0], [%1], 16, %2;" :: "r"(dst), "l"(src), "r"(sz));
}
__device__ __forceinline__ void ldsm4(uint32_t* r, uint32_t addr) {
    asm volatile("ldmatrix.sync.aligned.m8n8.x4.shared.b16 {%0,%1,%2,%3}, [%4];"
                 : "=r"(r[0]), "=r"(r[1]), "=r"(r[2]), "=r"(r[3]) : "r"(addr));
}
__device__ __forceinline__ void mma16(float* c, const uint32_t* a, uint32_t b0, uint32_t b1) {
    asm volatile("mma.sync.aligned.m16n8k16.row.col.f32.f16.f16.f32 "
                 "{%0,%1,%2,%3},{%4,%5,%6,%7},{%8,%9},{%0,%1,%2,%3};"
                 : "+f"(c[0]), "+f"(c[1]), "+f"(c[2]), "+f"(c[3])
                 : "r"(a[0]), "r"(a[1]), "r"(a[2]), "r"(a[3]), "r"(b0), "r"(b1));
}

// ---- prepass: x NCHW -> NHWC fp16 (8B stores), and w[k][n] -> [n][k'] fp16 ----
__global__ void prepass_kernel(const float* __restrict__ x, const float* __restrict__ w) {
    __shared__ float t[32][33];
    const int tid = threadIdx.x;
    const int tx = tid & 31, ty = tid >> 5;
    const int bx = blockIdx.x;
    if (bx < NXBLK) {
        const int n  = bx / 392;
        const int r  = bx - n * 392;
        const int p0 = (r % 98) * 32;
        const int c0 = (r / 98) * 32;
        const float* xp = x + ((size_t)n * 128 + c0) * HW + p0;
#pragma unroll
        for (int i = ty; i < 32; i += 8)
            t[i][tx] = xp[(size_t)i * HW + tx];     // t[ch][pix]
        __syncthreads();
        const int prow = tid >> 3, cq = tid & 7;
        __half h0 = __float2half_rn(t[cq * 4 + 0][prow]);
        __half h1 = __float2half_rn(t[cq * 4 + 1][prow]);
        __half h2 = __float2half_rn(t[cq * 4 + 2][prow]);
        __half h3 = __float2half_rn(t[cq * 4 + 3][prow]);
        Half4 v{__halves2half2(h0, h1), __halves2half2(h2, h3)};
        __half* xo = g_xh + ((size_t)n * HW + p0 + prow) * 128 + c0 + cq * 4;
        *reinterpret_cast<Half4*>(xo) = v;
    } else {
        const int idx = bx - NXBLK;
        const int kp0 = (idx % 36) * 32;
        const int n0  = (idx / 36) * 32;
        for (int i = ty; i < 32; i += 8) {
            int kp = kp0 + i;
            int rr = kp >> 7, c = kp & 127;
            t[i][tx] = w[(c * 9 + rr) * 256 + n0 + tx];
        }
        __syncthreads();
        for (int i = ty; i < 32; i += 8)
            g_wh[(size_t)(n0 + i) * 1152 + kp0 + tx] = __float2half_rn(t[tx][i]);
    }
}

// ---- main kernel: CTA 128x256, 8 warps x (64x64) ----
__global__ __launch_bounds__(256, 1)
void conv_mma_kernel(const float* __restrict__ bias, float* __restrict__ out) {
    extern __shared__ char smem[];
    const uint32_t sb = s2u(smem);
    const int tid = threadIdx.x, wid = tid >> 5, lid = tid & 31;
    const int bx = blockIdx.x;              // 784 M-tiles

    // A producer: arow = tid>>1 (0..127), qh picks 4 of 8 chunks
    const int arow = tid >> 1, qh = tid & 1;
    const int p = bx * 128 + arow;
    const int nimg = p / HW;
    const int rem = p - nimg * HW;
    const int yp = rem / 56, xp = rem - yp * 56;
    const __half* xrow = g_xh + ((size_t)nimg * HW + (yp - 1) * 56 + (xp - 1)) * 128;
    // B producer: each thread owns cout row = tid (8 chunks)
    const __half* wrow = g_wh + (size_t)tid * 1152;

    uint32_t dstA[4], dstB[8];
#pragma unroll
    for (int j = 0; j < 4; j++)
        dstA[j] = swz(arow * 128 + (qh * 4 + j) * 16);
#pragma unroll
    for (int j = 0; j < 8; j++)
        dstB[j] = swz(tid * 128 + j * 16);

    auto issue = [&](int kt, int buf) {
        const int r = kt >> 1;
        const int kh = r / 3, kw = r - kh * 3;
        const int cb = (kt & 1) * 64;
        const bool ok = ((unsigned)(yp + kh - 1) < 56u) && ((unsigned)(xp + kw - 1) < 56u);
        const __half* asrc = ok ? (xrow + (kh * 56 + kw) * 128 + cb) : g_xh;
        const int sz = ok ? 16 : 0;
        const uint32_t ad = sb + buf * STG;
        const uint32_t bd = ad + 16384;
        const __half* bsrc = wrow + kt * 64;
#pragma unroll
        for (int j = 0; j < 4; j++)
            cp16(ad + dstA[j], asrc + (ok ? (qh * 4 + j) * 8 : 0), sz);
#pragma unroll
        for (int j = 0; j < 8; j++)
            cp16(bd + dstB[j], bsrc + j * 8, 16);
        asm volatile("cp.async.commit_group;" ::: "memory");
    };

    issue(0, 0);
    issue(1, 1);

    float acc[4][8][4];
#pragma unroll
    for (int i = 0; i < 4; i++)
#pragma unroll
        for (int j = 0; j < 8; j++)
#pragma unroll
            for (int q = 0; q < 4; q++) acc[i][j][q] = 0.f;

    const int m0  = (wid & 1) * 64;          // 2 m-warps
    const int n0w = (wid >> 1) * 64;         // 4 n-warps
    const int rowL = lid & 15;
    const int colL = (lid >> 4) * 16;

    int buf = 0, pbuf = 2;
    for (int kt = 0; kt < KT; kt++) {
        if (kt < KT - 1) asm volatile("cp.async.wait_group 1;" ::: "memory");
        else             asm volatile("cp.async.wait_group 0;" ::: "memory");
        __syncthreads();
        if (kt + 2 < KT) issue(kt + 2, pbuf);

        const uint32_t aT = sb + buf * STG;
        const uint32_t bT = aT + 16384;
#pragma unroll
        for (int s = 0; s < 4; s++) {
            uint32_t a[4][4], b[4][4];
#pragma unroll
            for (int mi = 0; mi < 4; mi++)
                ldsm4(a[mi], aT + swz((m0 + mi * 16 + rowL) * 128 + s * 32 + colL));
#pragma unroll
            for (int nj = 0; nj < 4; nj++)
                ldsm4(b[nj], bT + swz((n0w + nj * 16 + rowL) * 128 + s * 32 + colL));
#pragma unroll
            for (int mi = 0; mi < 4; mi++)
#pragma unroll
                for (int ni = 0; ni < 8; ni++)
                    mma16(acc[mi][ni], a[mi], b[ni >> 1][ni & 1], b[ni >> 1][(ni & 1) + 2]);
        }
        buf  = (buf == 2)  ? 0 : buf + 1;
        pbuf = (pbuf == 2) ? 0 : pbuf + 1;
    }

    // ---- epilogue: acc -> smem [channel][pixel] -> coalesced float4 NCHW stores ----
    __syncthreads();
    float* sc = reinterpret_cast<float*>(smem);   // [256][EPAD] floats (135KB)

#pragma unroll
    for (int mi = 0; mi < 4; mi++) {
        const int mr = m0 + mi * 16 + (lid >> 2);
#pragma unroll
        for (int ni = 0; ni < 8; ni++) {
            const int c0 = n0w + ni * 8 + (lid & 3) * 2;
            sc[c0 * EPAD + mr]           = acc[mi][ni][0];
            sc[(c0 + 1) * EPAD + mr]     = acc[mi][ni][1];
            sc[c0 * EPAD + mr + 8]       = acc[mi][ni][2];
            sc[(c0 + 1) * EPAD + mr + 8] = acc[mi][ni][3];
        }
    }
    __syncthreads();

    const int base = bx * 128;
    const int img0 = base / HW;
    const int off0 = base - img0 * HW;
#pragma unroll
    for (int j = 0; j < 32; j++) {
        const int c = wid * 32 + j;
        float4 v = *reinterpret_cast<const float4*>(&sc[c * EPAD + lid * 4]);
        const float bb = bias[c];
        v.x += bb; v.y += bb; v.z += bb; v.w += bb;
        int pix = off0 + lid * 4;
        int img = img0;
        if (pix >= HW) { pix -= HW; img++; }
        *reinterpret_cast<float4*>(out + ((size_t)(img * 256 + c)) * HW + pix) = v;
    }
}

extern "C" void kernel_launch(void* const* d_in, const int* in_sizes, int n_in,
                              void* d_out, int out_size) {
    const float* x    = (const float*)d_in[0];
    const float* w    = (const float*)d_in[1];
    const float* bias = (const float*)d_in[2];
    float* out        = (float*)d_out;

    cudaFuncSetAttribute(conv_mma_kernel, cudaFuncAttributeMaxDynamicSharedMemorySize, SMEM_DYN);

    prepass_kernel<<<NXBLK + 288, 256>>>(x, w);
    conv_mma_kernel<<<784, 256, SMEM_DYN>>>(bias, out);
}